// round 17
// baseline (speedup 1.0000x reference)
#include <cuda_runtime.h>
#include <cuda_bf16.h>

#define THREADS   256
#define ITEMS     8
#define FULLMASK  0xffffffffu
#define INIT_FLOATS_PER_BLOCK (THREADS * 4)   // 1024 floats per init block

__device__ unsigned g_init_ctr;   // zero-initialized at module load; self-resetting
__device__ unsigned g_done_ctr;

__global__ __launch_bounds__(THREADS)
void spmv_fused_kernel(const float* __restrict__ vals,
                       const float* __restrict__ x,
                       const int*   __restrict__ rows,
                       const int*   __restrict__ cols,
                       const float* __restrict__ bias,
                       float*       __restrict__ y,
                       unsigned nnz, unsigned n_rows,
                       unsigned initBlocks, unsigned gridTotal) {
    const unsigned tid  = blockIdx.x * THREADS + threadIdx.x;
    const unsigned base = tid * ITEMS;
    const int lane = threadIdx.x & 31;
    const unsigned warpBase = (tid & ~31u) * ITEMS;
    const bool warpFull = (warpBase + 32u * ITEMS) <= nnz;

    // ---- Phase 1: first initBlocks blocks copy their bias slice into y ----
    if (blockIdx.x < initBlocks) {
        unsigned s = blockIdx.x * INIT_FLOATS_PER_BLOCK + threadIdx.x * 4;
        if (s + 4 <= n_rows) {
            float4 b = *reinterpret_cast<const float4*>(bias + s);
            *reinterpret_cast<float4*>(y + s) = b;
        } else if (s < n_rows) {
            for (unsigned k = s; k < n_rows; k++) y[k] = bias[k];
        }
        __threadfence();               // publish y stores to L2 (gpu scope)
        __syncthreads();               // all block's stores fenced before signal
        if (threadIdx.x == 0) atomicAdd(&g_init_ctr, 1u);
    }

    // ---- Phase 2: front-load all y-independent memory work ----
    int   r[ITEMS];
    float v[ITEMS];
    float xv[ITEMS];
    bool tailActive = false;
    unsigned tailCnt = 0;

    if (warpFull) {
        const int4*   rp = reinterpret_cast<const int4*>(rows + base);
        const int4*   cp = reinterpret_cast<const int4*>(cols + base);
        const float4* vp = reinterpret_cast<const float4*>(vals + base);

        int4   c0 = __ldcs(&cp[0]);
        int4   c1 = __ldcs(&cp[1]);
        int4   r0 = __ldcs(&rp[0]);
        int4   r1 = __ldcs(&rp[1]);
        float4 v0 = __ldcs(&vp[0]);
        float4 v1 = __ldcs(&vp[1]);

        xv[0] = __ldg(&x[c0.x]);
        xv[1] = __ldg(&x[c0.y]);
        xv[2] = __ldg(&x[c0.z]);
        xv[3] = __ldg(&x[c0.w]);
        xv[4] = __ldg(&x[c1.x]);
        xv[5] = __ldg(&x[c1.y]);
        xv[6] = __ldg(&x[c1.z]);
        xv[7] = __ldg(&x[c1.w]);

        r[0]=r0.x; r[1]=r0.y; r[2]=r0.z; r[3]=r0.w;
        r[4]=r1.x; r[5]=r1.y; r[6]=r1.z; r[7]=r1.w;
        v[0]=v0.x; v[1]=v0.y; v[2]=v0.z; v[3]=v0.w;
        v[4]=v1.x; v[5]=v1.y; v[6]=v1.z; v[7]=v1.w;
    } else if (base < nnz) {
        tailActive = true;
        tailCnt = nnz - base;
        if (tailCnt > ITEMS) tailCnt = ITEMS;
        for (unsigned k = 0; k < tailCnt; k++) {
            r[k]  = rows[base + k];
            int c = cols[base + k];
            v[k]  = vals[base + k];
            xv[k] = __ldg(&x[c]);
        }
    }

    // ---- Phase 3: device-side dependency — wait until all init blocks done ----
    if (threadIdx.x == 0) {
        while (__ldcg(&g_init_ctr) < initBlocks) __nanosleep(64);
    }
    __syncthreads();
    __threadfence();   // acquire: order the spin before our y atomics

    // ---- Phase 4: segment scan + reduction (y atomics now safe) ----
    if (warpFull) {
        float acc = 0.0f;
        int   cur = r[0];
        #pragma unroll
        for (int i = 0; i < ITEMS; i++) {
            if (r[i] != cur) {
                atomicAdd(&y[cur], acc);
                acc = 0.0f;
                cur = r[i];
            }
            acc = fmaf(v[i], xv[i], acc);
        }

        // Warp segmented inclusive scan over tail accumulators.
        int lrprev = __shfl_up_sync(FULLMASK, cur, 1);
        unsigned headf = (lane == 0) || (cur != lrprev);

        float    vsum = acc;
        unsigned stop = headf;
        #pragma unroll
        for (int d = 1; d < 32; d <<= 1) {
            float    pv = __shfl_up_sync(FULLMASK, vsum, d);
            unsigned ps = __shfl_up_sync(FULLMASK, stop, d);
            if (lane >= d && !stop) { vsum += pv; stop = ps; }
        }
        unsigned hnext = __shfl_down_sync(FULLMASK, headf, 1);
        if (lane == 31 || hnext) atomicAdd(&y[cur], vsum);
    } else if (tailActive) {
        float acc = 0.0f;
        int   cur = r[0];
        for (unsigned k = 0; k < tailCnt; k++) {
            if (r[k] != cur) {
                atomicAdd(&y[cur], acc);
                acc = 0.0f;
                cur = r[k];
            }
            acc = fmaf(v[k], xv[k], acc);
        }
        atomicAdd(&y[cur], acc);
    }

    // ---- Phase 5: self-resetting counters (last block zeroes both) ----
    __syncthreads();
    if (threadIdx.x == 0) {
        unsigned d = atomicAdd(&g_done_ctr, 1u);
        if (d == gridTotal - 1u) {
            atomicExch(&g_init_ctr, 0u);   // L2-level, visible to next replay
            atomicExch(&g_done_ctr, 0u);
        }
    }
}

extern "C" void kernel_launch(void* const* d_in, const int* in_sizes, int n_in,
                              void* d_out, int out_size) {
    // metadata order: vals[NNZ] f32, x[N_COLS] f32, bias[N_ROWS] f32,
    //                 rows[NNZ] i32, cols[NNZ] i32, n_rows (ignored)
    const float* vals = (const float*)d_in[0];
    const float* x    = (const float*)d_in[1];
    const float* bias = (const float*)d_in[2];
    const int*   rows = (const int*)d_in[3];
    const int*   cols = (const int*)d_in[4];
    float* y = (float*)d_out;

    unsigned nnz    = (unsigned)in_sizes[0];
    unsigned n_rows = (unsigned)in_sizes[2];

    unsigned chunks     = (nnz + ITEMS - 1) / ITEMS;
    unsigned grid       = (chunks + THREADS - 1) / THREADS;
    unsigned initBlocks = (n_rows + INIT_FLOATS_PER_BLOCK - 1) / INIT_FLOATS_PER_BLOCK;
    if (grid < initBlocks) grid = initBlocks;   // defensive (not hit here: 6250 >= 196)

    spmv_fused_kernel<<<grid, THREADS>>>(vals, x, rows, cols, bias, y,
                                         nnz, n_rows, initBlocks, grid);
}